// round 5
// baseline (speedup 1.0000x reference)
#include <cuda_runtime.h>
#include <cuda_bf16.h>
#include <cstdint>
#include <cstddef>
#include <math.h>

// Problem constants
constexpr int B_  = 2;
constexpr int T_  = 2048;
constexpr int HID = 2048;
constexpr int NH  = 16;
constexpr int NKV = 4;
constexpr int HD  = 128;
constexpr int GK  = 2048;   // K dim of every projection GEMM

// ---------------- scratch (static device arrays; no allocation) ----------------
__device__ float        g_Qf[(size_t)B_ * T_ * NH  * HD];
__device__ float        g_Kf[(size_t)B_ * T_ * NKV * HD];
__device__ float        g_Vf[(size_t)B_ * T_ * NKV * HD];
__device__ __nv_bfloat16 g_Qh[(size_t)B_ * NH  * T_ * HD];
__device__ __nv_bfloat16 g_Ql[(size_t)B_ * NH  * T_ * HD];
__device__ __nv_bfloat16 g_Kh[(size_t)B_ * NKV * T_ * HD];
__device__ __nv_bfloat16 g_Kl[(size_t)B_ * NKV * T_ * HD];
__device__ __nv_bfloat16 g_Vh[(size_t)B_ * NKV * T_ * HD];
__device__ __nv_bfloat16 g_Vl[(size_t)B_ * NKV * T_ * HD];
// split inputs / outputs for GEMMs
__device__ __nv_bfloat16 g_xh[(size_t)B_ * T_ * HID];
__device__ __nv_bfloat16 g_xl[(size_t)B_ * T_ * HID];
__device__ __nv_bfloat16 g_Oh[(size_t)B_ * T_ * NH * HD];
__device__ __nv_bfloat16 g_Ol[(size_t)B_ * T_ * NH * HD];
// transposed + split weights [N][K]
__device__ __nv_bfloat16 g_wqt_h[(size_t)HID * HID];
__device__ __nv_bfloat16 g_wqt_l[(size_t)HID * HID];
__device__ __nv_bfloat16 g_wkt_h[(size_t)(NKV*HD) * HID];
__device__ __nv_bfloat16 g_wkt_l[(size_t)(NKV*HD) * HID];
__device__ __nv_bfloat16 g_wvt_h[(size_t)(NKV*HD) * HID];
__device__ __nv_bfloat16 g_wvt_l[(size_t)(NKV*HD) * HID];
__device__ __nv_bfloat16 g_wot_h[(size_t)HID * HID];
__device__ __nv_bfloat16 g_wot_l[(size_t)HID * HID];

// ---------------- PTX helpers ----------------
__device__ __forceinline__ uint32_t smem_u32(const void* p) {
    return (uint32_t)__cvta_generic_to_shared(p);
}
__device__ __forceinline__ void ldsm4(uint32_t r[4], const void* p) {
    uint32_t a = smem_u32(p);
    asm volatile("ldmatrix.sync.aligned.m8n8.x4.shared.b16 {%0,%1,%2,%3}, [%4];"
                 : "=r"(r[0]), "=r"(r[1]), "=r"(r[2]), "=r"(r[3]) : "r"(a));
}
__device__ __forceinline__ void ldsm4t(uint32_t r[4], const void* p) {
    uint32_t a = smem_u32(p);
    asm volatile("ldmatrix.sync.aligned.m8n8.x4.trans.shared.b16 {%0,%1,%2,%3}, [%4];"
                 : "=r"(r[0]), "=r"(r[1]), "=r"(r[2]), "=r"(r[3]) : "r"(a));
}
__device__ __forceinline__ void mma_bf16(float c[4], const uint32_t a[4], uint32_t b0, uint32_t b1) {
    asm volatile("mma.sync.aligned.m16n8k16.row.col.f32.bf16.bf16.f32 "
                 "{%0,%1,%2,%3}, {%4,%5,%6,%7}, {%8,%9}, {%0,%1,%2,%3};"
                 : "+f"(c[0]), "+f"(c[1]), "+f"(c[2]), "+f"(c[3])
                 : "r"(a[0]), "r"(a[1]), "r"(a[2]), "r"(a[3]), "r"(b0), "r"(b1));
}
__device__ __forceinline__ void cpasync16(uint32_t saddr, const void* g) {
    asm volatile("cp.async.cg.shared.global [%0], [%1], 16;" :: "r"(saddr), "l"(g));
}
__device__ __forceinline__ void cpcommit() { asm volatile("cp.async.commit_group;"); }
template <int N> __device__ __forceinline__ void cpwait() {
    asm volatile("cp.async.wait_group %0;" :: "n"(N));
}
__device__ __forceinline__ void split2(float a, float b, uint32_t& hv, uint32_t& lv) {
    __nv_bfloat162 h = __floats2bfloat162_rn(a, b);
    float2 f = __bfloat1622float2(h);
    __nv_bfloat162 l = __floats2bfloat162_rn(a - f.x, b - f.y);
    hv = *reinterpret_cast<uint32_t*>(&h);
    lv = *reinterpret_cast<uint32_t*>(&l);
}
__device__ __forceinline__ void split_store4(float4 v, __nv_bfloat16* hi, __nv_bfloat16* lo) {
    uint32_t h0, l0, h1, l1;
    split2(v.x, v.y, h0, l0);
    split2(v.z, v.w, h1, l1);
    *reinterpret_cast<uint2*>(hi) = make_uint2(h0, h1);
    *reinterpret_cast<uint2*>(lo) = make_uint2(l0, l1);
}

// =====================================================================
// prep: split x into bf16 hi/lo
// =====================================================================
__global__ void split_x_kernel(const float4* __restrict__ X,
                               __nv_bfloat16* __restrict__ xh, __nv_bfloat16* __restrict__ xl)
{
    int i = blockIdx.x * 256 + threadIdx.x;
    float4 v = X[i];
    split_store4(v, xh + (size_t)i * 4, xl + (size_t)i * 4);
}

// =====================================================================
// prep: transpose weight [K=2048][N] -> [N][K=2048] and split hi/lo
// =====================================================================
__global__ void transpose_split_w(const float* __restrict__ W,
                                  __nv_bfloat16* __restrict__ Th, __nv_bfloat16* __restrict__ Tl,
                                  int N)
{
    __shared__ float tile[32][33];
    int k0 = blockIdx.x * 32, n0 = blockIdx.y * 32;
    int tx = threadIdx.x, ty = threadIdx.y;   // 32 x 8
#pragma unroll
    for (int i = 0; i < 32; i += 8)
        tile[ty + i][tx] = W[(size_t)(k0 + ty + i) * N + n0 + tx];
    __syncthreads();
#pragma unroll
    for (int i = 0; i < 32; i += 8) {
        float v = tile[tx][ty + i];
        __nv_bfloat16 hh = __float2bfloat16(v);
        size_t o = (size_t)(n0 + ty + i) * GK + k0 + tx;
        Th[o] = hh;
        Tl[o] = __float2bfloat16(v - __bfloat162float(hh));
    }
}

// =====================================================================
// classic-mma GEMM on pre-split operands:
// C[M,N] = A[M,K] * B^T, A=[M,K] hi/lo bf16, B=[N,K] hi/lo bf16 (K-major)
// CTA 128x128, 512 threads (16 warps, 4x4), warp tile 32x32,
// K-chunks of 64, 2-stage cp.async pipeline.
// =====================================================================
constexpr int KC    = 64;
constexpr int GST   = 72;                 // smem row stride in halves (64+8)
constexpr int OPSZ  = 128 * GST;          // 9216 halves per operand tile
constexpr int STSZ  = 4 * OPSZ;           // 36864 halves per stage (Ah,Al,Bh,Bl)
constexpr int GEMM_SMEM = 2 * STSZ * 2;   // 147456 bytes

__global__ __launch_bounds__(512, 1)
void gemm_sp(const __nv_bfloat16* __restrict__ Ah, const __nv_bfloat16* __restrict__ Al,
             const __nv_bfloat16* __restrict__ Bh, const __nv_bfloat16* __restrict__ Bl,
             float* __restrict__ C, int N)
{
    extern __shared__ __nv_bfloat16 smh[];
    const int tid  = threadIdx.x;
    const int lane = tid & 31;
    const int wid  = tid >> 5;           // 0..15
    const int bn   = blockIdx.x, bm = blockIdx.y;
    const int wm   = (wid >> 2) * 32;
    const int wn   = (wid & 3) * 32;
    const uint32_t sb = smem_u32(smh);

    const __nv_bfloat16* ops[4] = {
        Ah + (size_t)bm * 128 * GK, Al + (size_t)bm * 128 * GK,
        Bh + (size_t)bn * 128 * GK, Bl + (size_t)bn * 128 * GK
    };

    auto fill = [&](int chunk, int st) {
        uint32_t base = sb + st * (STSZ * 2);
        int k0 = chunk * KC;
#pragma unroll
        for (int i = 0; i < 8; i++) {
            int c  = i * 512 + tid;        // 4096 x 16B
            int op = c >> 10;
            int r  = (c >> 3) & 127;
            int ch = c & 7;
            uint32_t dst = base + (op * OPSZ + r * GST + ch * 8) * 2;
            cpasync16(dst, ops[op] + (size_t)r * GK + k0 + ch * 8);
        }
        cpcommit();
    };

    float acc[2][4][4] = {};

    fill(0, 0);
    const int NC = GK / KC;   // 32
    for (int i = 0; i < NC; i++) {
        const int s = i & 1;
        if (i + 1 < NC) { fill(i + 1, s ^ 1); cpwait<1>(); }
        else            { cpwait<0>(); }
        __syncthreads();

        const __nv_bfloat16* st = smh + s * STSZ;
#pragma unroll
        for (int ks = 0; ks < 4; ks++) {
            const int col = ks * 16 + ((lane >> 4) << 3);
            uint32_t af[2][2][4];
#pragma unroll
            for (int mf = 0; mf < 2; mf++) {
                int row = wm + mf * 16 + (lane & 15);
                ldsm4(af[0][mf], st + 0 * OPSZ + row * GST + col);
                ldsm4(af[1][mf], st + 1 * OPSZ + row * GST + col);
            }
            uint32_t bf[2][2][4];
#pragma unroll
            for (int nf2 = 0; nf2 < 2; nf2++) {
                int row = wn + nf2 * 16 + (lane & 15);
                ldsm4(bf[0][nf2], st + 2 * OPSZ + row * GST + col);
                ldsm4(bf[1][nf2], st + 3 * OPSZ + row * GST + col);
            }
#pragma unroll
            for (int mf = 0; mf < 2; mf++) {
#pragma unroll
                for (int nf = 0; nf < 4; nf++) {
                    int nf2 = nf >> 1, sub = nf & 1;
                    uint32_t b0h = bf[0][nf2][sub],     b1h = bf[0][nf2][sub + 2];
                    uint32_t b0l = bf[1][nf2][sub],     b1l = bf[1][nf2][sub + 2];
                    mma_bf16(acc[mf][nf], af[0][mf], b0h, b1h);
                    mma_bf16(acc[mf][nf], af[0][mf], b0l, b1l);
                    mma_bf16(acc[mf][nf], af[1][mf], b0h, b1h);
                }
            }
        }
        __syncthreads();
    }

#pragma unroll
    for (int mf = 0; mf < 2; mf++) {
        int r0 = bm * 128 + wm + mf * 16 + (lane >> 2);
#pragma unroll
        for (int nf = 0; nf < 4; nf++) {
            int c = bn * 128 + wn + (nf >> 1) * 16 + (nf & 1) * 8 + (lane & 3) * 2;
            *(float2*)(C + (size_t)r0 * N + c)       = make_float2(acc[mf][nf][0], acc[mf][nf][1]);
            *(float2*)(C + (size_t)(r0 + 8) * N + c) = make_float2(acc[mf][nf][2], acc[mf][nf][3]);
        }
    }
}

// =====================================================================
// Fused RoPE + scale + bf16 hi/lo split + relayout for Q, K, V in one launch
// =====================================================================
constexpr int NQE = B_ * T_ * NH * HD;    // 8388608
constexpr int NKE = B_ * T_ * NKV * HD;   // 2097152

__device__ __forceinline__ void rope_one(
    const float* __restrict__ src, const float* __restrict__ cosb, const float* __restrict__ sinb,
    __nv_bfloat16* __restrict__ dh, __nv_bfloat16* __restrict__ dl,
    int idx, int H, int do_rope, float scale)
{
    int d    = idx & 127;
    int rest = idx >> 7;
    int h    = rest % H;
    int bt   = rest / H;
    int t    = bt & (T_ - 1);
    int b    = bt >> 11;

    float v = src[idx];
    float o;
    if (do_rope) {
        int dd = d & 63;
        float c = cosb[t * 64 + dd], s = sinb[t * 64 + dd];
        if (d < 64) { float v2 = src[idx + 64]; o = v * c - v2 * s; }
        else        { float v1 = src[idx - 64]; o = v * c + v1 * s; }
    } else {
        o = v;
    }
    o *= scale;
    __nv_bfloat16 hh = __float2bfloat16(o);
    size_t di = (((size_t)(b * H + h)) * T_ + t) * HD + d;
    dh[di] = hh;
    dl[di] = __float2bfloat16(o - __bfloat162float(hh));
}

__global__ void rope_all(const float* __restrict__ Qf, const float* __restrict__ Kf,
                         const float* __restrict__ Vf,
                         const float* __restrict__ cosb, const float* __restrict__ sinb,
                         __nv_bfloat16* __restrict__ Qh, __nv_bfloat16* __restrict__ Ql,
                         __nv_bfloat16* __restrict__ Kh, __nv_bfloat16* __restrict__ Kl,
                         __nv_bfloat16* __restrict__ Vh, __nv_bfloat16* __restrict__ Vl,
                         float qsc)
{
    int idx = blockIdx.x * 256 + threadIdx.x;
    if (idx < NQE) {
        rope_one(Qf, cosb, sinb, Qh, Ql, idx, NH, 1, qsc);
    } else if (idx < NQE + NKE) {
        rope_one(Kf, cosb, sinb, Kh, Kl, idx - NQE, NKV, 1, 1.0f);
    } else {
        rope_one(Vf, cosb, sinb, Vh, Vl, idx - NQE - NKE, NKV, 0, 1.0f);
    }
}

// =====================================================================
// Flash attention (causal, GQA). Br=128 (8 warps x 16 rows), Bc=64.
// Output written directly as split bf16 hi/lo [B*T, 2048].
// =====================================================================
constexpr int AS        = 136;
constexpr int Q_H_OFF   = 0;
constexpr int Q_L_OFF   = 128 * AS;
constexpr int STAGE_OFF = 2 * 128 * AS;
constexpr int STAGE_SZ  = 4 * 64 * AS;
constexpr int ATTN_SMEM_BYTES = (STAGE_OFF + 2 * STAGE_SZ) * 2;

__global__ __launch_bounds__(256, 1) void attn_kernel(
    const __nv_bfloat16* __restrict__ Qh, const __nv_bfloat16* __restrict__ Ql,
    const __nv_bfloat16* __restrict__ Kh, const __nv_bfloat16* __restrict__ Kl,
    const __nv_bfloat16* __restrict__ Vh, const __nv_bfloat16* __restrict__ Vl,
    __nv_bfloat16* __restrict__ Oh, __nv_bfloat16* __restrict__ Ol)
{
    extern __shared__ __nv_bfloat16 sm[];
    const int tid  = threadIdx.x;
    const int lane = tid & 31;
    const int wid  = tid >> 5;
    const int bh   = blockIdx.y;
    const int b    = bh >> 4, h = bh & 15;
    const int qi   = (int)gridDim.x - 1 - (int)blockIdx.x;
    const int qbase = qi * 128;
    const int kvi  = b * NKV + (h >> 2);

    const __nv_bfloat16* qh_g = Qh + ((size_t)bh * T_ + qbase) * HD;
    const __nv_bfloat16* ql_g = Ql + ((size_t)bh * T_ + qbase) * HD;
    const __nv_bfloat16* ks_g[4] = {
        Kh + (size_t)kvi * T_ * HD, Kl + (size_t)kvi * T_ * HD,
        Vh + (size_t)kvi * T_ * HD, Vl + (size_t)kvi * T_ * HD
    };

#pragma unroll
    for (int i = 0; i < 16; i++) {
        int c = i * 256 + tid;
        int split = c >> 11, cc = c & 2047;
        int row = cc >> 4, ch = cc & 15;
        const __nv_bfloat16* src = (split ? ql_g : qh_g) + row * HD + ch * 8;
        cpasync16(smem_u32(sm + (split ? Q_L_OFF : Q_H_OFF) + row * AS + ch * 8), src);
    }
    auto loadKV = [&](int j, int s) {
        size_t gb = (size_t)j * 64 * HD;
        int so = STAGE_OFF + s * STAGE_SZ;
#pragma unroll
        for (int i = 0; i < 16; i++) {
            int c = i * 256 + tid;
            int which = c >> 10, cc = c & 1023;
            int row = cc >> 4, ch = cc & 15;
            cpasync16(smem_u32(sm + so + which * (64 * AS) + row * AS + ch * 8),
                      ks_g[which] + gb + row * HD + ch * 8);
        }
    };
    loadKV(0, 0);
    cpcommit();

    float m0 = -1e30f, m1 = -1e30f, l0 = 0.f, l1 = 0.f;
    float o[16][4];
#pragma unroll
    for (int i = 0; i < 16; i++)
#pragma unroll
        for (int j = 0; j < 4; j++) o[i][j] = 0.f;

    const int nj = 2 * qi + 2;
    const int rowbase = qbase + wid * 16;

    for (int j = 0; j < nj; j++) {
        const int s = j & 1;
        if (j + 1 < nj) { loadKV(j + 1, s ^ 1); cpcommit(); cpwait<1>(); }
        else            { cpwait<0>(); }
        __syncthreads();

        const int kb = STAGE_OFF + s * STAGE_SZ;

        float sacc[8][4];
#pragma unroll
        for (int i = 0; i < 8; i++)
#pragma unroll
            for (int jj = 0; jj < 4; jj++) sacc[i][jj] = 0.f;

#pragma unroll
        for (int ks = 0; ks < 8; ks++) {
            uint32_t qa[2][4];
            {
                int row = wid * 16 + (lane & 15);
                int col = ks * 16 + ((lane >> 4) << 3);
                ldsm4(qa[0], sm + Q_H_OFF + row * AS + col);
                ldsm4(qa[1], sm + Q_L_OFF + row * AS + col);
            }
#pragma unroll
            for (int nf2 = 0; nf2 < 4; nf2++) {
                uint32_t kh4[4], kl4[4];
                int krow = nf2 * 16 + (lane & 15);
                int kcol = ks * 16 + ((lane >> 4) << 3);
                ldsm4(kh4, sm + kb + krow * AS + kcol);
                ldsm4(kl4, sm + kb + 64 * AS + krow * AS + kcol);
                mma_bf16(sacc[2 * nf2],     qa[0], kh4[0], kh4[2]);
                mma_bf16(sacc[2 * nf2],     qa[0], kl4[0], kl4[2]);
                mma_bf16(sacc[2 * nf2],     qa[1], kh4[0], kh4[2]);
                mma_bf16(sacc[2 * nf2 + 1], qa[0], kh4[1], kh4[3]);
                mma_bf16(sacc[2 * nf2 + 1], qa[0], kl4[1], kl4[3]);
                mma_bf16(sacc[2 * nf2 + 1], qa[1], kh4[1], kh4[3]);
            }
        }

        const int kvb = j * 64;
        if (kvb + 63 > rowbase) {
            int r0 = rowbase + (lane >> 2), r1 = r0 + 8;
#pragma unroll
            for (int nf = 0; nf < 8; nf++) {
                int c0 = kvb + nf * 8 + (lane & 3) * 2;
                if (c0 > r0)     sacc[nf][0] = -1e30f;
                if (c0 + 1 > r0) sacc[nf][1] = -1e30f;
                if (c0 > r1)     sacc[nf][2] = -1e30f;
                if (c0 + 1 > r1) sacc[nf][3] = -1e30f;
            }
        }

        float rm0 = -1e30f, rm1 = -1e30f;
#pragma unroll
        for (int nf = 0; nf < 8; nf++) {
            rm0 = fmaxf(rm0, fmaxf(sacc[nf][0], sacc[nf][1]));
            rm1 = fmaxf(rm1, fmaxf(sacc[nf][2], sacc[nf][3]));
        }
        rm0 = fmaxf(rm0, __shfl_xor_sync(0xffffffffu, rm0, 1));
        rm0 = fmaxf(rm0, __shfl_xor_sync(0xffffffffu, rm0, 2));
        rm1 = fmaxf(rm1, __shfl_xor_sync(0xffffffffu, rm1, 1));
        rm1 = fmaxf(rm1, __shfl_xor_sync(0xffffffffu, rm1, 2));
        float mn0 = fmaxf(m0, rm0), mn1 = fmaxf(m1, rm1);
        float corr0 = exp2f(m0 - mn0), corr1 = exp2f(m1 - mn1);
        m0 = mn0; m1 = mn1;

        float rs0 = 0.f, rs1 = 0.f;
#pragma unroll
        for (int nf = 0; nf < 8; nf++) {
            float p0 = exp2f(sacc[nf][0] - mn0);
            float p1 = exp2f(sacc[nf][1] - mn0);
            float p2 = exp2f(sacc[nf][2] - mn1);
            float p3 = exp2f(sacc[nf][3] - mn1);
            sacc[nf][0] = p0; sacc[nf][1] = p1; sacc[nf][2] = p2; sacc[nf][3] = p3;
            rs0 += p0 + p1; rs1 += p2 + p3;
        }
        l0 = l0 * corr0 + rs0;
        l1 = l1 * corr1 + rs1;
#pragma unroll
        for (int df = 0; df < 16; df++) {
            o[df][0] *= corr0; o[df][1] *= corr0;
            o[df][2] *= corr1; o[df][3] *= corr1;
        }

        uint32_t ph[4][4], pl[4][4];
#pragma unroll
        for (int kk = 0; kk < 4; kk++) {
            const float* A0 = sacc[2 * kk];
            const float* A1 = sacc[2 * kk + 1];
            split2(A0[0], A0[1], ph[kk][0], pl[kk][0]);
            split2(A0[2], A0[3], ph[kk][1], pl[kk][1]);
            split2(A1[0], A1[1], ph[kk][2], pl[kk][2]);
            split2(A1[2], A1[3], ph[kk][3], pl[kk][3]);
        }

        const int vb = kb + 2 * 64 * AS;
#pragma unroll
        for (int kk = 0; kk < 4; kk++) {
#pragma unroll
            for (int nf2 = 0; nf2 < 8; nf2++) {
                uint32_t vh4[4], vl4[4];
                int vrow = kk * 16 + (lane & 15);
                int vcol = nf2 * 16 + ((lane >> 4) << 3);
                ldsm4t(vh4, sm + vb + vrow * AS + vcol);
                ldsm4t(vl4, sm + vb + 64 * AS + vrow * AS + vcol);
                mma_bf16(o[2 * nf2],     ph[kk], vh4[0], vh4[1]);
                mma_bf16(o[2 * nf2],     ph[kk], vl4[0], vl4[1]);
                mma_bf16(o[2 * nf2],     pl[kk], vh4[0], vh4[1]);
                mma_bf16(o[2 * nf2 + 1], ph[kk], vh4[2], vh4[3]);
                mma_bf16(o[2 * nf2 + 1], ph[kk], vl4[2], vl4[3]);
                mma_bf16(o[2 * nf2 + 1], pl[kk], vh4[2], vh4[3]);
            }
        }
        __syncthreads();
    }

    l0 += __shfl_xor_sync(0xffffffffu, l0, 1);
    l0 += __shfl_xor_sync(0xffffffffu, l0, 2);
    l1 += __shfl_xor_sync(0xffffffffu, l1, 1);
    l1 += __shfl_xor_sync(0xffffffffu, l1, 2);
    float inv0 = 1.f / l0, inv1 = 1.f / l1;

    int r0 = rowbase + (lane >> 2);
    size_t base0 = ((size_t)b * T_ + r0) * HID + h * HD + (lane & 3) * 2;
    size_t base1 = base0 + (size_t)8 * HID;
#pragma unroll
    for (int df = 0; df < 16; df++) {
        uint32_t hv, lv;
        split2(o[df][0] * inv0, o[df][1] * inv0, hv, lv);
        *(uint32_t*)(Oh + base0 + df * 8) = hv;
        *(uint32_t*)(Ol + base0 + df * 8) = lv;
        split2(o[df][2] * inv1, o[df][3] * inv1, hv, lv);
        *(uint32_t*)(Oh + base1 + df * 8) = hv;
        *(uint32_t*)(Ol + base1 + df * 8) = lv;
    }
}

// =====================================================================
// host launcher
// =====================================================================
extern "C" void kernel_launch(void* const* d_in, const int* in_sizes, int n_in,
                              void* d_out, int out_size)
{
    const float* x    = (const float*)d_in[0];
    const float* cosb = (const float*)d_in[1];
    const float* sinb = (const float*)d_in[2];
    const float* wq   = (const float*)d_in[3];
    const float* wk   = (const float*)d_in[4];
    const float* wv   = (const float*)d_in[5];
    const float* wo   = (const float*)d_in[6];

    float *Qf, *Kf, *Vf;
    __nv_bfloat16 *Qh, *Ql, *Kh, *Kl, *Vh, *Vl, *xh, *xl, *Oh, *Ol;
    __nv_bfloat16 *wqt_h, *wqt_l, *wkt_h, *wkt_l, *wvt_h, *wvt_l, *wot_h, *wot_l;
    cudaGetSymbolAddress((void**)&Qf, g_Qf);
    cudaGetSymbolAddress((void**)&Kf, g_Kf);
    cudaGetSymbolAddress((void**)&Vf, g_Vf);
    cudaGetSymbolAddress((void**)&Qh, g_Qh);
    cudaGetSymbolAddress((void**)&Ql, g_Ql);
    cudaGetSymbolAddress((void**)&Kh, g_Kh);
    cudaGetSymbolAddress((void**)&Kl, g_Kl);
    cudaGetSymbolAddress((void**)&Vh, g_Vh);
    cudaGetSymbolAddress((void**)&Vl, g_Vl);
    cudaGetSymbolAddress((void**)&xh, g_xh);
    cudaGetSymbolAddress((void**)&xl, g_xl);
    cudaGetSymbolAddress((void**)&Oh, g_Oh);
    cudaGetSymbolAddress((void**)&Ol, g_Ol);
    cudaGetSymbolAddress((void**)&wqt_h, g_wqt_h);
    cudaGetSymbolAddress((void**)&wqt_l, g_wqt_l);
    cudaGetSymbolAddress((void**)&wkt_h, g_wkt_h);
    cudaGetSymbolAddress((void**)&wkt_l, g_wkt_l);
    cudaGetSymbolAddress((void**)&wvt_h, g_wvt_h);
    cudaGetSymbolAddress((void**)&wvt_l, g_wvt_l);
    cudaGetSymbolAddress((void**)&wot_h, g_wot_h);
    cudaGetSymbolAddress((void**)&wot_l, g_wot_l);

    cudaFuncSetAttribute(attn_kernel, cudaFuncAttributeMaxDynamicSharedMemorySize,
                         ATTN_SMEM_BYTES);
    cudaFuncSetAttribute(gemm_sp, cudaFuncAttributeMaxDynamicSharedMemorySize, GEMM_SMEM);

    const int M = B_ * T_;  // 4096

    // prep: split x; transpose+split weights                              // launches 0-4
    split_x_kernel<<<(M * HID) / 4 / 256, 256>>>((const float4*)x, xh, xl);
    transpose_split_w<<<dim3(GK / 32, HID / 32), dim3(32, 8)>>>(wq, wqt_h, wqt_l, HID);
    transpose_split_w<<<dim3(GK / 32, (NKV * HD) / 32), dim3(32, 8)>>>(wk, wkt_h, wkt_l, NKV * HD);
    transpose_split_w<<<dim3(GK / 32, (NKV * HD) / 32), dim3(32, 8)>>>(wv, wvt_h, wvt_l, NKV * HD);
    transpose_split_w<<<dim3(GK / 32, HID / 32), dim3(32, 8)>>>(wo, wot_h, wot_l, HID);

    // projections (launch 5 = gemmQ -> ncu capture target)
    gemm_sp<<<dim3(HID / 128, M / 128), 512, GEMM_SMEM>>>(xh, xl, wqt_h, wqt_l, Qf, HID);
    gemm_sp<<<dim3((NKV * HD) / 128, M / 128), 512, GEMM_SMEM>>>(xh, xl, wkt_h, wkt_l, Kf, NKV * HD);
    gemm_sp<<<dim3((NKV * HD) / 128, M / 128), 512, GEMM_SMEM>>>(xh, xl, wvt_h, wvt_l, Vf, NKV * HD);

    // rope + split + relayout (fold softmax scale * log2(e) into Q)
    float qsc = (1.0f / sqrtf((float)HD)) * 1.4426950408889634f;
    rope_all<<<(NQE + 2 * NKE) / 256, 256>>>(Qf, Kf, Vf, cosb, sinb,
                                             Qh, Ql, Kh, Kl, Vh, Vl, qsc);

    // attention (writes split bf16 output)
    attn_kernel<<<dim3(T_ / 128, B_ * NH), 256, ATTN_SMEM_BYTES>>>(Qh, Ql, Kh, Kl, Vh, Vl, Oh, Ol);

    // output projection
    gemm_sp<<<dim3(HID / 128, M / 128), 512, GEMM_SMEM>>>(Oh, Ol, wot_h, wot_l, (float*)d_out, HID);
}